// round 11
// baseline (speedup 1.0000x reference)
#include <cuda_runtime.h>
#include <cuda_fp16.h>
#include <math.h>
#include <stdint.h>

#define Bq   128
#define Tq   512
#define Iq   512
#define Hq   1024
#define G4   4096
#define TGTq 512
#define NB   65536   // Tq * Bq
#define NCTA 128

// ---------------- persistent-kernel SMEM layout (A resident) -------------
#define PA          1032                   // A row pitch (halves): 1024 + 8 pad
#define SMEM_PERS   (64 * PA * 2 + 16)     // 132112 B -> 1 CTA/SM guaranteed

// ---------------- xproj GEMM SMEM layout ---------------------------------
#define SP          72
#define REG_BYTES   (128 * SP * 2)         // 18432
#define XBUF_BYTES  (3 * REG_BYTES)        // Ah, Al, Bx
#define SMEM_XP     (2 * XBUF_BYTES)       // 110592 B

// ---------------------------------------------------------------------------
// Persistent device scratch (no cudaMalloc allowed)
// ---------------------------------------------------------------------------
__device__ __align__(16) __half g_Wr_h[(size_t)G4 * Hq];   // Whh fp16 (single)
__device__ __align__(16) __half g_Wi_h[(size_t)G4 * Iq];   // Wih hi
__device__ __align__(16) __half g_Wi_l[(size_t)G4 * Iq];   // Wih lo
__device__ __align__(16) __half g_xh[(size_t)NB * Iq];     // x fp16 [t*128+b][i]
// h in paired B-fragment layout: [buf][(kb*8+bp)*32+lane] =
//  {bg_even.r0, bg_even.r1, bg_odd.r0, bg_odd.r1}  (kb = 16 hidden units,
//  bp = pair of batch groups of 8, lane = fragment lane)
__device__ __align__(16) uint4 g_hB[2][64 * 8 * 32];
__device__ float g_hf[Hq * Bq];                            // [u][b] final h
__device__ float g_xp[(size_t)G4 * NB];                    // x-proj [row][t*128+b]
__device__ unsigned g_cnt[8];
__device__ unsigned g_cnt2;
__device__ unsigned g_gen;

// ---------------------------------------------------------------------------
// PTX helpers (plain sm_100 feature set)
// ---------------------------------------------------------------------------
__device__ __forceinline__ uint32_t smem_u32(const void* p) {
    uint32_t a;
    asm("{ .reg .u64 t; cvta.to.shared.u64 t, %1; cvt.u32.u64 %0, t; }"
        : "=r"(a) : "l"(p));
    return a;
}
__device__ __forceinline__ void ldsm4(uint32_t* r, uint32_t addr) {
    asm volatile("ldmatrix.sync.aligned.m8n8.x4.shared.b16 {%0,%1,%2,%3}, [%4];"
                 : "=r"(r[0]), "=r"(r[1]), "=r"(r[2]), "=r"(r[3]) : "r"(addr));
}
__device__ __forceinline__ void ldsm2(uint32_t* r, uint32_t addr) {
    asm volatile("ldmatrix.sync.aligned.m8n8.x2.shared.b16 {%0,%1}, [%2];"
                 : "=r"(r[0]), "=r"(r[1]) : "r"(addr));
}
__device__ __forceinline__ void mma16816(float* c, const uint32_t* a, const uint32_t* b) {
    asm volatile(
        "mma.sync.aligned.m16n8k16.row.col.f32.f16.f16.f32 "
        "{%0,%1,%2,%3}, {%4,%5,%6,%7}, {%8,%9}, {%0,%1,%2,%3};"
        : "+f"(c[0]), "+f"(c[1]), "+f"(c[2]), "+f"(c[3])
        : "r"(a[0]), "r"(a[1]), "r"(a[2]), "r"(a[3]), "r"(b[0]), "r"(b[1]));
}
__device__ __forceinline__ void ldg_cg_v4(uint4& v, const uint4* p) {
    asm volatile("ld.global.cg.v4.u32 {%0,%1,%2,%3}, [%4];"
                 : "=r"(v.x), "=r"(v.y), "=r"(v.z), "=r"(v.w) : "l"(p));
}
#define CP16(d, s) \
    asm volatile("cp.async.cg.shared.global [%0], [%1], 16;" :: "r"(d), "l"(s) : "memory")
#define CPCOMMIT() asm volatile("cp.async.commit_group;" ::: "memory")

__device__ __forceinline__ float sigf(float x) {
    return __fdividef(1.0f, 1.0f + __expf(-x));
}
__device__ __forceinline__ float tanhfast(float x) {
    return __fdividef(2.0f, 1.0f + __expf(-2.0f * x)) - 1.0f;
}

// two-level sense-reversing grid barrier (8 groups of 16 CTAs)
__device__ __forceinline__ void gbar() {
    __syncthreads();
    if (threadIdx.x == 0) {
        unsigned gen;
        asm volatile("ld.acquire.gpu.global.u32 %0, [%1];"
                     : "=r"(gen) : "l"(&g_gen) : "memory");
        __threadfence();
        unsigned grp = blockIdx.x >> 4;
        if (atomicAdd(&g_cnt[grp], 1u) == 15u) {
            atomicExch(&g_cnt[grp], 0u);
            if (atomicAdd(&g_cnt2, 1u) == 7u) {
                atomicExch(&g_cnt2, 0u);
                __threadfence();
                asm volatile("st.release.gpu.global.u32 [%0], %1;"
                             :: "l"(&g_gen), "r"(gen + 1) : "memory");
            }
        }
        unsigned cur;
        do {
            asm volatile("ld.acquire.gpu.global.u32 %0, [%1];"
                         : "=r"(cur) : "l"(&g_gen) : "memory");
            if (cur != gen) break;
            asm volatile("nanosleep.u32 32;");
        } while (1);
    }
    __syncthreads();
}

// ---------------------------------------------------------------------------
// Prep kernels
// ---------------------------------------------------------------------------
__global__ void k_prep_w(const float* __restrict__ Wih, const float* __restrict__ Whh) {
    int r = blockIdx.x;
    for (int k = threadIdx.x; k < Hq; k += 256) {
        g_Wr_h[(size_t)r * Hq + k] = __float2half_rn(Whh[(size_t)r * Hq + k]);
    }
    for (int k = threadIdx.x; k < Iq; k += 256) {
        float w = Wih[(size_t)r * Iq + k];
        __half hi = __float2half_rn(w);
        g_Wi_h[(size_t)r * Iq + k] = hi;
        g_Wi_l[(size_t)r * Iq + k] = __float2half_rn(w - __half2float(hi));
    }
}

__global__ void k_prep_x(const float* __restrict__ XW) {
    int bx = blockIdx.x;          // t*128 + b
    int t = bx >> 7, b = bx & 127;
    const float* __restrict__ src = XW + ((size_t)b * Tq + t) * Iq;
    size_t doff = (size_t)bx * Iq;
    for (int i = threadIdx.x; i < Iq; i += 256) {
        g_xh[doff + i] = __float2half_rn(src[i]);
    }
}

__global__ void k_init() {
    if (blockIdx.x == 0 && threadIdx.x < 8) g_cnt[threadIdx.x] = 0;
    if (blockIdx.x == 0 && threadIdx.x == 8) { g_cnt2 = 0; g_gen = 0; }
    int n = 64 * 8 * 32;
    uint4 z = make_uint4(0, 0, 0, 0);
    for (int i = blockIdx.x * blockDim.x + threadIdx.x; i < n;
         i += gridDim.x * blockDim.x) {
        g_hB[0][i] = z;
        g_hB[1][i] = z;
    }
}

// ---------------------------------------------------------------------------
// x-projection GEMM (fp16 2-term split on W): g_xp = Wih * x^T
// grid (32, 512): C tile 128(M of 4096) x 128(N of 65536), K=512.
// ---------------------------------------------------------------------------
__global__ __launch_bounds__(256) void k_xproj() {
    extern __shared__ __align__(128) uint8_t smem[];
    const uint32_t sb = smem_u32(smem);
    const int tid = threadIdx.x;
    const int L = tid & 31, w = tid >> 5;
    const int mw = w & 3, nw = w >> 2;   // warp tile M32 x N64

    const int mrow0 = blockIdx.x * 128;
    const int nrow0 = blockIdx.y * 128;
    const int lsc = tid & 7;

    const uint32_t a_off = ((mw * 32 + (L & 15)) * SP + (L >> 4) * 8) * 2;
    const uint32_t b_off = ((nw * 64 + (L & 7)) * SP + ((L >> 3) & 1) * 8) * 2;

    float acc[2][8][4];
#pragma unroll
    for (int mi = 0; mi < 2; mi++)
#pragma unroll
        for (int nj = 0; nj < 8; nj++)
#pragma unroll
            for (int q = 0; q < 4; q++) acc[mi][nj][q] = 0.0f;

    auto load_chunk = [&](int buf, int ch) {
        const int gk = ch * 64 + lsc * 8;
        const uint32_t dstbase = sb + buf * XBUF_BYTES;
#pragma unroll
        for (int i = 0; i < 4; i++) {
            int row = (tid >> 3) + i * 32;
            uint32_t doff = (uint32_t)row * 144 + lsc * 16;
            size_t ao = (size_t)(mrow0 + row) * Iq + gk;
            size_t bo = (size_t)(nrow0 + row) * Iq + gk;
            CP16(dstbase + 0 * REG_BYTES + doff, g_Wi_h + ao);
            CP16(dstbase + 1 * REG_BYTES + doff, g_Wi_l + ao);
            CP16(dstbase + 2 * REG_BYTES + doff, g_xh + bo);
        }
        CPCOMMIT();
    };

    load_chunk(0, 0);
    load_chunk(1, 1);
    for (int c = 0; c < 8; c++) {
        if (c < 7) asm volatile("cp.async.wait_group 1;" ::: "memory");
        else       asm volatile("cp.async.wait_group 0;" ::: "memory");
        __syncthreads();
        const uint32_t base = sb + (c & 1) * XBUF_BYTES;
#pragma unroll
        for (int ki = 0; ki < 4; ki++) {
            uint32_t ah[2][4], al[2][4], bh[8][2];
#pragma unroll
            for (int mi = 0; mi < 2; mi++) {
                uint32_t ad = base + a_off + (mi * 16 * SP + ki * 16) * 2;
                ldsm4(ah[mi], ad);
                ldsm4(al[mi], ad + REG_BYTES);
            }
#pragma unroll
            for (int nj = 0; nj < 8; nj++) {
                uint32_t bd = base + 2 * REG_BYTES + b_off + (nj * 8 * SP + ki * 16) * 2;
                ldsm2(bh[nj], bd);
            }
#pragma unroll
            for (int mi = 0; mi < 2; mi++)
#pragma unroll
                for (int nj = 0; nj < 8; nj++) {
                    mma16816(acc[mi][nj], ah[mi], bh[nj]);
                    mma16816(acc[mi][nj], al[mi], bh[nj]);
                }
        }
        if (c + 2 < 8) {
            __syncthreads();
            load_chunk(c & 1, c + 2);
        }
    }

#pragma unroll
    for (int mi = 0; mi < 2; mi++)
#pragma unroll
        for (int nj = 0; nj < 8; nj++) {
            int row = mrow0 + mw * 32 + mi * 16 + (L >> 2);
            int col = nrow0 + nw * 64 + nj * 8 + (L & 3) * 2;
            float* p = g_xp + (size_t)row * NB + col;
            *(float2*)p            = make_float2(acc[mi][nj][0], acc[mi][nj][1]);
            *(float2*)(p + 8 * NB) = make_float2(acc[mi][nj][2], acc[mi][nj][3]);
        }
}

// ---------------------------------------------------------------------------
// Persistent recurrence, M64 x N64 per CTA. 128 CTAs = 64 M-tiles x 2 N-tiles.
// CTA (cm, cn): 16 units u = cm*16..cm*16+15, batch cols cn*64..cn*64+63.
// A rows interleaved: CTA row = mw*16 + ju*4 + g (4 units x 4 gates per strip).
// 8 warps = 4 M-strips (mw) x 2 N-groups (nw), warp tile M16 x N32.
// B (h, fp16) in paired-quad fragment layout, ld.cg.v4 register ring.
// Gates transposed within lane-quads via shfl; cell state in registers.
// ---------------------------------------------------------------------------
__global__ __launch_bounds__(256, 1) void k_recur(const float* __restrict__ bih,
                                                  const float* __restrict__ bhh) {
    extern __shared__ __align__(128) uint8_t smem[];
    const uint32_t sb = smem_u32(smem);
    const int tid = threadIdx.x;
    const int L = tid & 31;
    const int w = tid >> 5;
    const int mw = w & 3;                // M strip (16 rows)
    const int nw = w >> 2;               // N group (32 cols)
    const int cm = blockIdx.x >> 1;
    const int cn = blockIdx.x & 1;

    // ---- load resident A: 64 rows x 1024 halves, interleaved row order ----
    {
        int row = tid >> 2;              // 0..63
        int seg = tid & 3;
        int g = row & 3, ju = (row >> 2) & 3, mwr = row >> 4;
        size_t grow = ((size_t)g * Hq + cm * 16 + mwr * 4 + ju) * Hq;
#pragma unroll
        for (int it = 0; it < 32; it++) {
            int s16 = seg + it * 4;      // 0..127 16B segments per row
            CP16(sb + (uint32_t)row * (PA * 2) + s16 * 16, g_Wr_h + grow + s16 * 8);
        }
        CPCOMMIT();
    }

    // per-thread cell ownership (gate slot s transposes to full cells)
    const int s = (L >> 2) & 3;          // this lane's gate in the C fragment
    const int qbase = L & ~12;           // quad-group base lane
    const int ju_own = ((L >> 4) & 1) + ((s >> 1) << 1);
    const int u = cm * 16 + mw * 4 + ju_own;
    const int col0 = cn * 64 + nw * 32 + (L & 3) * 2 + (s & 1);

    float bias[4], cc[4];
#pragma unroll
    for (int g = 0; g < 4; g++) {
        bias[g] = bih[g * Hq + u] + bhh[g * Hq + u];
        cc[g] = 0.0f;                    // cc indexed by nj
    }

    // producer store mapping (4 cells: cols col0 + nj*8)
    const int k_local = u & 15;
    const int pLf = (k_local & 7) >> 1;                       // lane low bits
    const int p_by = ((k_local >> 3) << 2) | ((k_local & 1) << 1); // byte in 8B half

    const uint32_t aoff = ((uint32_t)(mw * 16 + (L & 15)) * PA + (L >> 4) * 8) * 2;
    const int bpBase = cn * 4 + nw * 2;

    asm volatile("cp.async.wait_group 0;" ::: "memory");
    __syncthreads();

    // xp prefetch for first step: [gate][nj]
    float xpv[4][4];
#pragma unroll
    for (int g = 0; g < 4; g++)
#pragma unroll
        for (int nj = 0; nj < 4; nj++)
            xpv[g][nj] = g_xp[(size_t)(g * Hq + u) * NB + (Tq - 1) * Bq + col0 + nj * 8];

    for (int st = 0; st < Tq; st++) {
        const uint4* __restrict__ hBin = g_hB[st & 1];
        uint4* __restrict__ hBout      = g_hB[(st + 1) & 1];

        float acc[4][4];                 // [nj][frag]
#pragma unroll
        for (int nj = 0; nj < 4; nj++)
#pragma unroll
            for (int q = 0; q < 4; q++) acc[nj][q] = 0.0f;

        uint4 Bp[3][8];                  // 3-slot ring, compile-time indices

#define LOADB(G, SLOT)                                                        \
        {                                                                     \
            _Pragma("unroll")                                                 \
            for (int kk = 0; kk < 4; kk++)                                    \
                _Pragma("unroll")                                             \
                for (int p = 0; p < 2; p++)                                   \
                    ldg_cg_v4(Bp[SLOT][kk * 2 + p],                           \
                              hBin + ((((G) * 4 + kk) * 8 + bpBase + p) * 32 + L)); \
        }

        LOADB(0, 0); LOADB(1, 1);

#pragma unroll
        for (int g = 0; g < 16; g++) {
            if (g + 2 < 16) {
                const int ng = g + 2;
                const int ns = ng % 3;
                LOADB(ng, ns);
            }
            const int slot = g % 3;
#pragma unroll
            for (int kk = 0; kk < 4; kk++) {
                const int k = (g * 4 + kk) * 16;
                uint32_t a4[4];
                ldsm4(a4, sb + aoff + (uint32_t)k * 2);
#pragma unroll
                for (int nj = 0; nj < 4; nj++) {
                    const int p = nj >> 1;
                    uint32_t bh[2];
                    if (nj & 1) { bh[0] = Bp[slot][kk * 2 + p].z; bh[1] = Bp[slot][kk * 2 + p].w; }
                    else        { bh[0] = Bp[slot][kk * 2 + p].x; bh[1] = Bp[slot][kk * 2 + p].y; }
                    mma16816(acc[nj], a4, bh);
                }
            }
        }
#undef LOADB

        // ---- gate transpose within lane quads: owner s keeps round r==s ----
        float gates[4][4];               // [nj][gate]
#pragma unroll
        for (int nj = 0; nj < 4; nj++)
#pragma unroll
            for (int r = 0; r < 4; r++) {
                float pub = acc[nj][r];
#pragma unroll
                for (int g = 0; g < 4; g++) {
                    float v = __shfl_sync(0xffffffffu, pub, qbase + (g << 2));
                    if (s == r) gates[nj][g] = v;
                }
            }

        // ---- register-local cell update for 4 (col) cells of unit u ----
        const bool last = (st == Tq - 1);
#pragma unroll
        for (int nj = 0; nj < 4; nj++) {
            int b = col0 + nj * 8;
            float ig = sigf(gates[nj][0] + xpv[0][nj] + bias[0]);
            float fg = sigf(gates[nj][1] + xpv[1][nj] + bias[1]);
            float gg = tanhfast(gates[nj][2] + xpv[2][nj] + bias[2]);
            float og = sigf(gates[nj][3] + xpv[3][nj] + bias[3]);
            float cv = fg * cc[nj] + ig * gg;
            cc[nj] = cv;
            float h = og * tanhfast(cv);
            int Lf = ((b & 7) << 2) | pLf;
            char* qp = (char*)&hBout[((size_t)cm * 8 + (b >> 4)) * 32 + Lf];
            *(__half*)(qp + ((b >> 3) & 1) * 8 + p_by) = __float2half_rn(h);
            if (last) g_hf[u * Bq + b] = h;
        }

        // prefetch next step's xp before the barrier
        if (!last) {
            const int tn = Tq - 2 - st;
#pragma unroll
            for (int g = 0; g < 4; g++)
#pragma unroll
                for (int nj = 0; nj < 4; nj++)
                    xpv[g][nj] = g_xp[(size_t)(g * Hq + u) * NB + tn * Bq + col0 + nj * 8];
            gbar();
        }
    }
}

// ---------------------------------------------------------------------------
// Final linear
// ---------------------------------------------------------------------------
__global__ __launch_bounds__(256) void k_lin(const float* __restrict__ Wlin,
                                             const float* __restrict__ blin,
                                             float* __restrict__ out) {
    int gid = blockIdx.x * blockDim.x + threadIdx.x;
    int b = gid & (Bq - 1);
    int tgt = gid >> 7;
    float acc = blin[tgt];
    const float* __restrict__ wrow = Wlin + (size_t)tgt * Hq;
#pragma unroll 8
    for (int k = 0; k < Hq; k++) {
        acc += g_hf[k * Bq + b] * wrow[k];
    }
    out[(size_t)b * TGTq + tgt] = acc;
}

// ---------------------------------------------------------------------------
extern "C" void kernel_launch(void* const* d_in, const int* in_sizes, int n_in,
                              void* d_out, int out_size)
{
    const float* XW   = (const float*)d_in[0];
    const float* Wih  = (const float*)d_in[1];
    const float* Whh  = (const float*)d_in[2];
    const float* bih  = (const float*)d_in[3];
    const float* bhh  = (const float*)d_in[4];
    const float* Wlin = (const float*)d_in[5];
    const float* blin = (const float*)d_in[6];
    float* out = (float*)d_out;

    cudaFuncSetAttribute(k_xproj, cudaFuncAttributeMaxDynamicSharedMemorySize, SMEM_XP);
    cudaFuncSetAttribute(k_recur, cudaFuncAttributeMaxDynamicSharedMemorySize, SMEM_PERS);

    k_prep_w<<<G4, 256>>>(Wih, Whh);
    k_prep_x<<<NB, 256>>>(XW);
    k_init<<<128, 256>>>();
    k_xproj<<<dim3(32, 512, 1), 256, SMEM_XP>>>();
    k_recur<<<NCTA, 256, SMEM_PERS>>>(bih, bhh);
    k_lin<<<(Bq * TGTq) / 256, 256>>>(Wlin, blin, out);
}